// round 1
// baseline (speedup 1.0000x reference)
#include <cuda_runtime.h>
#include <cuda_bf16.h>
#include <math.h>

// Problem constants (fixed shapes)
#define Bb 2
#define Tt 4096
#define Dd 2048
#define Hh 16
#define Kk 128
#define Vv 128
#define BT 64
#define NT 64
#define TOKS (Bb*Tt)          // 8192
#define HD   (Hh*Kk)          // 2048
#define VS   32               // v-slice width in scan
#define NVS  (Vv/VS)          // 4

// ---------------- scratch (device globals; no runtime alloc) ----------------
__device__ float g_q [TOKS*HD];
__device__ float g_k [TOKS*HD];
__device__ float g_v [TOKS*HD];
__device__ float g_g [TOKS*HD];
__device__ float g_z [TOKS*HD];
__device__ float g_og[TOKS*HD];
__device__ float g_eta  [TOKS*Hh];
__device__ float g_theta[TOKS*Hh];

// ---------------- GEMM: C[M,N] = alpha * A[M,Kd] @ B[N,Kd]^T ----------------
// 128x128 block tile, BK=16, 256 threads, 8x8 micro-tile (split 4+4 for banks)
__global__ __launch_bounds__(256, 2)
void gemm_tn(const float* __restrict__ A, const float* __restrict__ B,
             float* __restrict__ C, int M, int N, int Kd, float alpha)
{
    __shared__ float As[16][132];
    __shared__ float Bs[16][132];
    const int tid = threadIdx.x;
    const int tx  = tid & 15;
    const int ty  = tid >> 4;
    const int bm  = blockIdx.y * 128;
    const int bn  = blockIdx.x * 128;

    float acc[8][8];
#pragma unroll
    for (int i = 0; i < 8; i++)
#pragma unroll
        for (int j = 0; j < 8; j++) acc[i][j] = 0.f;

    const int lr = tid >> 1;          // row 0..127
    const int lc = (tid & 1) * 8;     // col 0 or 8

    const float* Ap = A + (size_t)(bm + lr) * Kd + lc;
    const float* Bp = B + (size_t)(bn + lr) * Kd + lc;

    for (int k0 = 0; k0 < Kd; k0 += 16) {
        float4 a0 = *(const float4*)(Ap + k0);
        float4 a1 = *(const float4*)(Ap + k0 + 4);
        float4 b0 = *(const float4*)(Bp + k0);
        float4 b1 = *(const float4*)(Bp + k0 + 4);
        As[lc+0][lr] = a0.x; As[lc+1][lr] = a0.y; As[lc+2][lr] = a0.z; As[lc+3][lr] = a0.w;
        As[lc+4][lr] = a1.x; As[lc+5][lr] = a1.y; As[lc+6][lr] = a1.z; As[lc+7][lr] = a1.w;
        Bs[lc+0][lr] = b0.x; Bs[lc+1][lr] = b0.y; Bs[lc+2][lr] = b0.z; Bs[lc+3][lr] = b0.w;
        Bs[lc+4][lr] = b1.x; Bs[lc+5][lr] = b1.y; Bs[lc+6][lr] = b1.z; Bs[lc+7][lr] = b1.w;
        __syncthreads();
#pragma unroll
        for (int kk = 0; kk < 16; kk++) {
            float a[8], b[8];
            *(float4*)&a[0] = *(float4*)&As[kk][ty*4];
            *(float4*)&a[4] = *(float4*)&As[kk][64 + ty*4];
            *(float4*)&b[0] = *(float4*)&Bs[kk][tx*4];
            *(float4*)&b[4] = *(float4*)&Bs[kk][64 + tx*4];
#pragma unroll
            for (int i = 0; i < 8; i++)
#pragma unroll
                for (int j = 0; j < 8; j++) acc[i][j] += a[i] * b[j];
        }
        __syncthreads();
    }

#pragma unroll
    for (int i = 0; i < 8; i++) {
        int row = bm + ((i < 4) ? (ty*4 + i) : (64 + ty*4 + (i-4)));
        float4 v0, v1;
        v0.x = alpha*acc[i][0]; v0.y = alpha*acc[i][1]; v0.z = alpha*acc[i][2]; v0.w = alpha*acc[i][3];
        v1.x = alpha*acc[i][4]; v1.y = alpha*acc[i][5]; v1.z = alpha*acc[i][6]; v1.w = alpha*acc[i][7];
        *(float4*)(C + (size_t)row * N + bn + tx*4)       = v0;
        *(float4*)(C + (size_t)row * N + bn + 64 + tx*4)  = v1;
    }
}

// ---------------- eta / theta: sigmoid projections (N=16 each) ----------------
__global__ __launch_bounds__(256)
void eta_theta_kernel(const float* __restrict__ X, const float* __restrict__ Weta,
                      const float* __restrict__ Wth, float* __restrict__ Eta,
                      float* __restrict__ Th)
{
    __shared__ float sx[Dd];
    const int tok = blockIdx.x, tid = threadIdx.x;
    for (int i = tid; i < Dd/4; i += 256)
        *(float4*)&sx[i*4] = *(const float4*)(X + (size_t)tok*Dd + i*4);
    __syncthreads();
    const int p  = tid >> 3;        // 0..31 (16 heads x 2)
    const int l8 = tid & 7;
    const int h = p & 15, which = p >> 4;
    const float* w = (which ? Wth : Weta) + (size_t)h * Dd;
    float s = 0.f;
    for (int i = l8*4; i < Dd; i += 32) {
        float4 xv = *(float4*)&sx[i];
        float4 wv = *(const float4*)(w + i);
        s += xv.x*wv.x + xv.y*wv.y + xv.z*wv.z + xv.w*wv.w;
    }
    s += __shfl_xor_sync(0xffffffffu, s, 4);
    s += __shfl_xor_sync(0xffffffffu, s, 2);
    s += __shfl_xor_sync(0xffffffffu, s, 1);
    if (l8 == 0) {
        float sig = 1.f / (1.f + expf(-s));
        if (which) Th[(size_t)tok*Hh + h] = 0.1f * sig;
        else       Eta[(size_t)tok*Hh + h] = sig;
    }
}

// ---------------- chunked fast-weight scan ----------------
// grid: (B*H, NVS). Each block owns W-slice [128k x VS v], runs NT chunks serially.
__global__ __launch_bounds__(256, 1)
void scan_kernel(const float* __restrict__ Q, const float* __restrict__ Kc,
                 const float* __restrict__ Vc, const float* __restrict__ Eta,
                 const float* __restrict__ Th, float* __restrict__ Z)
{
    extern __shared__ float sm[];
    float* sWt   = sm;                    // [128][VS]   W^T slice: sWt[k*VS+v]
    float* sQ    = sWt  + 128*VS;         // [64][132]   q rows
    float* sKt   = sQ   + 64*132;         // [128][68]   k transposed: sKt[k*68+t]
    float* sVE   = sKt  + 128*68;         // [64][VS]    v, then e
    float* sM    = sVE  + 64*VS;          // [64][65]    qk*beta*theta_j
    float* sLec  = sM   + 64*65;          // [64]
    float* sElec = sLec + 64;             // [64]
    float* sCoef = sElec+ 64;             // [64]
    float* sTh   = sCoef+ 64;             // [64]

    const int tid = threadIdx.x;
    const int bh  = blockIdx.x;
    const int b = bh >> 4, h = bh & 15;
    const int vs0 = blockIdx.y * VS;

    const size_t tokbase = (size_t)b * Tt;
    const float* Qp = Q  + tokbase*HD + (size_t)h*Kk;
    const float* Kp = Kc + tokbase*HD + (size_t)h*Kk;
    const float* Vp = Vc + tokbase*HD + (size_t)h*Vv + vs0;
    float*       Zp = Z  + tokbase*HD + (size_t)h*Vv + vs0;

    for (int i = tid; i < 128*VS; i += 256) sWt[i] = 0.f;

    for (int ct = 0; ct < NT; ct++) {
        const int t0 = ct * BT;
        __syncthreads();   // protects sKt/sQ/sVE/sCoef from previous chunk's readers

        // ---- loads: Q,K full 128 cols; V slice; eta/theta ----
#pragma unroll
        for (int i = 0; i < 8; i++) {
            int idx = tid + i*256;          // 0..2047 float4 slots (64 rows x 32)
            int r = idx >> 5;
            int c = (idx & 31) << 2;
            float4 qv = *(const float4*)(Qp + (size_t)(t0+r)*HD + c);
            *(float4*)&sQ[r*132 + c] = qv;
            float4 kv = *(const float4*)(Kp + (size_t)(t0+r)*HD + c);
            sKt[(c+0)*68 + r] = kv.x;
            sKt[(c+1)*68 + r] = kv.y;
            sKt[(c+2)*68 + r] = kv.z;
            sKt[(c+3)*68 + r] = kv.w;
        }
#pragma unroll
        for (int i = 0; i < 2; i++) {
            int idx = tid + i*256;          // 0..511 (64 rows x 8 float4)
            int r = idx >> 3;
            int c = (idx & 7) << 2;
            *(float4*)&sVE[r*VS + c] = *(const float4*)(Vp + (size_t)(t0+r)*HD + c);
        }
        if (tid < 64) {
            size_t tk = (tokbase + t0 + tid) * Hh + h;
            sLec[tid] = logf(fmaxf(Eta[tk], 1e-8f));
            sTh[tid]  = Th[tk];
        }
        __syncthreads();
        if (tid == 0) {
            float c = 0.f;
            for (int t = 0; t < BT; t++) { c += sLec[t]; sLec[t] = c; }
        }
        __syncthreads();
        if (tid < 64) {
            float l = sLec[tid];
            sElec[tid] = expf(l);
            sCoef[tid] = expf(sLec[63] - l) * sTh[tid];
        }
        __syncthreads();

        // ---- Phase A1: e = k @ W^T - v   (in place over sVE) ----
        {
            const int tx = tid & 7, ty = tid >> 3;
            const int v0 = tx << 2;
            const int ta = ty*2, tb = ta + 1;
            float4 va = *(float4*)&sVE[ta*VS + v0];
            float4 vb = *(float4*)&sVE[tb*VS + v0];
            float a0[4] = {-va.x, -va.y, -va.z, -va.w};
            float a1[4] = {-vb.x, -vb.y, -vb.z, -vb.w};
#pragma unroll 8
            for (int kk = 0; kk < Kk; kk++) {
                float4 w = *(float4*)&sWt[kk*VS + v0];
                float ka = sKt[kk*68 + ta];
                float kb = sKt[kk*68 + tb];
                a0[0] += ka*w.x; a0[1] += ka*w.y; a0[2] += ka*w.z; a0[3] += ka*w.w;
                a1[0] += kb*w.x; a1[1] += kb*w.y; a1[2] += kb*w.z; a1[3] += kb*w.w;
            }
            float4 e0 = {a0[0],a0[1],a0[2],a0[3]};
            float4 e1 = {a1[0],a1[1],a1[2],a1[3]};
            *(float4*)&sVE[ta*VS + v0] = e0;
            *(float4*)&sVE[tb*VS + v0] = e1;
        }
        // ---- Phase A2: sM[i][j] = (q_i . k_j) * beta(i,j) * theta_j ----
        {
            const int tx = tid & 15, ty = tid >> 4;
            const int j0 = tx*4, i0 = ty*4;
            float acc[4][4];
#pragma unroll
            for (int i = 0; i < 4; i++)
#pragma unroll
                for (int j = 0; j < 4; j++) acc[i][j] = 0.f;
#pragma unroll 8
            for (int kk = 0; kk < Kk; kk++) {
                float4 bj = *(float4*)&sKt[kk*68 + j0];
                float ai0 = sQ[(i0+0)*132 + kk];
                float ai1 = sQ[(i0+1)*132 + kk];
                float ai2 = sQ[(i0+2)*132 + kk];
                float ai3 = sQ[(i0+3)*132 + kk];
                acc[0][0]+=ai0*bj.x; acc[0][1]+=ai0*bj.y; acc[0][2]+=ai0*bj.z; acc[0][3]+=ai0*bj.w;
                acc[1][0]+=ai1*bj.x; acc[1][1]+=ai1*bj.y; acc[1][2]+=ai1*bj.z; acc[1][3]+=ai1*bj.w;
                acc[2][0]+=ai2*bj.x; acc[2][1]+=ai2*bj.y; acc[2][2]+=ai2*bj.z; acc[2][3]+=ai2*bj.w;
                acc[3][0]+=ai3*bj.x; acc[3][1]+=ai3*bj.y; acc[3][2]+=ai3*bj.z; acc[3][3]+=ai3*bj.w;
            }
#pragma unroll
            for (int i = 0; i < 4; i++)
#pragma unroll
                for (int j = 0; j < 4; j++) {
                    int ii = i0 + i, jj = j0 + j;
                    float m = 0.f;
                    if (jj <= ii)
                        m = acc[i][j] * expf(fminf(sLec[ii] - sLec[jj], 0.f)) * sTh[jj];
                    sM[ii*65 + jj] = m;
                }
        }
        __syncthreads();

        // ---- Phase B: z = exp(lec)*(q @ W^T) - sM @ e ----
        {
            const int tx = tid & 7, ty = tid >> 3;
            const int v0 = tx << 2;
            const int ta = ty*2, tb = ta + 1;
            float z0[4] = {0,0,0,0}, z1[4] = {0,0,0,0};
#pragma unroll 8
            for (int kk = 0; kk < Kk; kk++) {
                float4 w = *(float4*)&sWt[kk*VS + v0];
                float qa = sQ[ta*132 + kk];
                float qb = sQ[tb*132 + kk];
                z0[0]+=qa*w.x; z0[1]+=qa*w.y; z0[2]+=qa*w.z; z0[3]+=qa*w.w;
                z1[0]+=qb*w.x; z1[1]+=qb*w.y; z1[2]+=qb*w.z; z1[3]+=qb*w.w;
            }
            float ea = sElec[ta], eb = sElec[tb];
#pragma unroll
            for (int j = 0; j < 4; j++) { z0[j] *= ea; z1[j] *= eb; }
#pragma unroll 8
            for (int j = 0; j < BT; j++) {
                float4 e4 = *(float4*)&sVE[j*VS + v0];
                float m0 = sM[ta*65 + j];
                float m1 = sM[tb*65 + j];
                z0[0]-=m0*e4.x; z0[1]-=m0*e4.y; z0[2]-=m0*e4.z; z0[3]-=m0*e4.w;
                z1[0]-=m1*e4.x; z1[1]-=m1*e4.y; z1[2]-=m1*e4.z; z1[3]-=m1*e4.w;
            }
            float4 o0 = {z0[0],z0[1],z0[2],z0[3]};
            float4 o1 = {z1[0],z1[1],z1[2],z1[3]};
            *(float4*)(Zp + (size_t)(t0+ta)*HD + v0) = o0;
            *(float4*)(Zp + (size_t)(t0+tb)*HD + v0) = o1;
        }
        __syncthreads();

        // ---- Phase C: W = W*exp(lec_end) - sum_t coef[t]*e[t,:]^T k[t,:] ----
        {
            const int tx = tid & 7, ty = tid >> 3;
            const int v0 = tx << 2, k0 = ty << 2;
            float acc[4][4];
#pragma unroll
            for (int i = 0; i < 4; i++)
#pragma unroll
                for (int j = 0; j < 4; j++) acc[i][j] = 0.f;
            const float decay = sElec[63];
#pragma unroll 4
            for (int t = 0; t < BT; t++) {
                float c = sCoef[t];
                float4 e4 = *(float4*)&sVE[t*VS + v0];
                float ce[4] = {c*e4.x, c*e4.y, c*e4.z, c*e4.w};
                float a0 = sKt[(k0+0)*68 + t];
                float a1 = sKt[(k0+1)*68 + t];
                float a2 = sKt[(k0+2)*68 + t];
                float a3 = sKt[(k0+3)*68 + t];
#pragma unroll
                for (int j = 0; j < 4; j++) {
                    acc[0][j] += a0*ce[j];
                    acc[1][j] += a1*ce[j];
                    acc[2][j] += a2*ce[j];
                    acc[3][j] += a3*ce[j];
                }
            }
#pragma unroll
            for (int i = 0; i < 4; i++) {
                float4 wv = *(float4*)&sWt[(k0+i)*VS + v0];
                wv.x = wv.x*decay - acc[i][0];
                wv.y = wv.y*decay - acc[i][1];
                wv.z = wv.z*decay - acc[i][2];
                wv.w = wv.w*decay - acc[i][3];
                *(float4*)&sWt[(k0+i)*VS + v0] = wv;
            }
        }
    }
}

// ---------------- gated RMS norm ----------------
__global__ __launch_bounds__(256)
void gated_rms_kernel(const float* __restrict__ Zin, const float* __restrict__ G,
                      const float* __restrict__ nw, float* __restrict__ OG)
{
    const int gw   = blockIdx.x * 8 + (threadIdx.x >> 5);   // (tok,h) group
    const int lane = threadIdx.x & 31;
    const size_t base = (size_t)gw * 128;
    float4 zv = *(const float4*)(Zin + base + lane*4);
    float ss = zv.x*zv.x + zv.y*zv.y + zv.z*zv.z + zv.w*zv.w;
#pragma unroll
    for (int o = 16; o; o >>= 1) ss += __shfl_xor_sync(0xffffffffu, ss, o);
    float r = rsqrtf(ss * (1.f/128.f) + 1e-5f);
    float4 gv = *(const float4*)(G  + base + lane*4);
    float4 wv = *(const float4*)(nw + lane*4);
    float4 o;
    o.x = zv.x*r*wv.x * (gv.x / (1.f + expf(-gv.x)));
    o.y = zv.y*r*wv.y * (gv.y / (1.f + expf(-gv.y)));
    o.z = zv.z*r*wv.z * (gv.z / (1.f + expf(-gv.z)));
    o.w = zv.w*r*wv.w * (gv.w / (1.f + expf(-gv.w)));
    *(float4*)(OG + base + lane*4) = o;
}

// ---------------- launch ----------------
extern "C" void kernel_launch(void* const* d_in, const int* in_sizes, int n_in,
                              void* d_out, int out_size)
{
    const float* X    = (const float*)d_in[0];
    const float* Wq   = (const float*)d_in[1];
    const float* Wk   = (const float*)d_in[2];
    const float* Wv   = (const float*)d_in[3];
    const float* Weta = (const float*)d_in[4];
    const float* Wth  = (const float*)d_in[5];
    const float* Wg   = (const float*)d_in[6];
    const float* nw   = (const float*)d_in[7];
    const float* Wo   = (const float*)d_in[8];
    float* out = (float*)d_out;

    float *q, *k, *v, *g, *z, *og, *eta, *th;
    cudaGetSymbolAddress((void**)&q,  g_q);
    cudaGetSymbolAddress((void**)&k,  g_k);
    cudaGetSymbolAddress((void**)&v,  g_v);
    cudaGetSymbolAddress((void**)&g,  g_g);
    cudaGetSymbolAddress((void**)&z,  g_z);
    cudaGetSymbolAddress((void**)&og, g_og);
    cudaGetSymbolAddress((void**)&eta,g_eta);
    cudaGetSymbolAddress((void**)&th, g_theta);

    const int scan_smem = (128*VS + 64*132 + 128*68 + 64*VS + 64*65 + 4*64) * 4;
    cudaFuncSetAttribute(scan_kernel, cudaFuncAttributeMaxDynamicSharedMemorySize, scan_smem);

    dim3 gg(HD/128, TOKS/128);   // (16, 64)
    const float qscale = 0.08838834764831845f;  // 128^-0.5

    gemm_tn<<<gg, 256>>>(X, Wq, q, TOKS, HD, Dd, qscale);
    gemm_tn<<<gg, 256>>>(X, Wk, k, TOKS, HD, Dd, 1.f);
    gemm_tn<<<gg, 256>>>(X, Wv, v, TOKS, HD, Dd, 1.f);
    gemm_tn<<<gg, 256>>>(X, Wg, g, TOKS, HD, Dd, 1.f);
    eta_theta_kernel<<<TOKS, 256>>>(X, Weta, Wth, eta, th);

    scan_kernel<<<dim3(Bb*Hh, NVS), 256, scan_smem>>>(q, k, v, eta, th, z);

    gated_rms_kernel<<<TOKS*Hh/8, 256>>>(z, g, nw, og);
    gemm_tn<<<gg, 256>>>(og, Wo, out, TOKS, HD, Dd, 1.f);
}

// round 3
// speedup vs baseline: 1.9779x; 1.9779x over previous
#include <cuda_runtime.h>
#include <cuda_bf16.h>
#include <math.h>
#include <cstdint>

// Problem constants (fixed shapes)
#define Bb 2
#define Tt 4096
#define Dd 2048
#define Hh 16
#define Kk 128
#define Vv 128
#define BT 64
#define NT 64
#define TOKS (Bb*Tt)          // 8192
#define HD   (Hh*Kk)          // 2048
#define VS   32               // v-slice width in scan
#define NVS  (Vv/VS)          // 4

// ---------------- scratch (device globals; no runtime alloc) ----------------
__device__ float g_q [TOKS*HD];
__device__ float g_k [TOKS*HD];
__device__ float g_v [TOKS*HD];
__device__ float g_g [TOKS*HD];
__device__ float g_z [TOKS*HD];
__device__ float g_eta  [TOKS*Hh];
__device__ float g_theta[TOKS*Hh];
__device__ __nv_bfloat16 g_xhi[TOKS*Dd];
__device__ __nv_bfloat16 g_xlo[TOKS*Dd];
__device__ __nv_bfloat16 g_whi[5*Dd*Dd];
__device__ __nv_bfloat16 g_wlo[5*Dd*Dd];
__device__ __nv_bfloat16 g_oghi[TOKS*HD];
__device__ __nv_bfloat16 g_oglo[TOKS*HD];

// ---------------- helpers ----------------
__device__ __forceinline__ uint32_t smem_u32(const void* p) {
    uint32_t a;
    asm("{ .reg .u64 t; cvta.to.shared.u64 t, %1; cvt.u32.u64 %0, t; }" : "=r"(a) : "l"(p));
    return a;
}
__device__ __forceinline__ void ldm_x4(uint32_t (&r)[4], uint32_t addr) {
    asm volatile("ldmatrix.sync.aligned.m8n8.x4.shared.b16 {%0,%1,%2,%3}, [%4];"
                 : "=r"(r[0]), "=r"(r[1]), "=r"(r[2]), "=r"(r[3]) : "r"(addr));
}
__device__ __forceinline__ void mma16816(float (&d)[4], const uint32_t (&a)[4],
                                         uint32_t b0, uint32_t b1) {
    asm volatile(
        "mma.sync.aligned.m16n8k16.row.col.f32.bf16.bf16.f32 "
        "{%0,%1,%2,%3}, {%4,%5,%6,%7}, {%8,%9}, {%0,%1,%2,%3};"
        : "+f"(d[0]), "+f"(d[1]), "+f"(d[2]), "+f"(d[3])
        : "r"(a[0]), "r"(a[1]), "r"(a[2]), "r"(a[3]), "r"(b0), "r"(b1));
}

// ---------------- fp32 -> (hi,lo) bf16 split ----------------
__global__ __launch_bounds__(256)
void split_bf16_kernel(const float* __restrict__ x, __nv_bfloat16* __restrict__ hi,
                       __nv_bfloat16* __restrict__ lo, int n4)
{
    int i = blockIdx.x * 256 + threadIdx.x;
    if (i >= n4) return;
    float4 v = ((const float4*)x)[i];
    float vv[4] = {v.x, v.y, v.z, v.w};
    __align__(8) __nv_bfloat16 h[4], l[4];
#pragma unroll
    for (int j = 0; j < 4; j++) {
        h[j] = __float2bfloat16(vv[j]);
        l[j] = __float2bfloat16(vv[j] - __bfloat162float(h[j]));
    }
    ((uint2*)hi)[i] = *(uint2*)h;
    ((uint2*)lo)[i] = *(uint2*)l;
}

// ---------------- HMMA 3xBF16 GEMM: C[8192,2048] = alpha * A @ B^T ----------------
// Logical K' = 3*2048 (segments hi*hi, hi*lo, lo*hi). CTA tile 128x128, BK=32,
// 4-stage cp.async pipeline, 8 warps (4M x 2N), warp tile 32x64.
#define BKT 32
#define NKT 192                 // 3 * (2048/32)
#define ROWB 80                 // smem row stride in bytes (32 bf16 + 8 pad)
#define STG_BYTES (128*ROWB*2)  // A tile + B tile = 20480
#define NSTG 4

__device__ __forceinline__ void ld_stage(uint32_t sA, uint32_t sB,
    const __nv_bfloat16* __restrict__ A, const __nv_bfloat16* __restrict__ B,
    int bm, int bn, int k0, int tid)
{
#pragma unroll
    for (int i = 0; i < 2; i++) {
        int idx = tid + i * 256;      // 0..511
        int row = idx >> 2, c = idx & 3;
        uint32_t dA = sA + row * ROWB + c * 16;
        const void* pA = A + (size_t)(bm + row) * 2048 + k0 + c * 8;
        asm volatile("cp.async.cg.shared.global [%0], [%1], 16;" :: "r"(dA), "l"(pA) : "memory");
        uint32_t dB = sB + row * ROWB + c * 16;
        const void* pB = B + (size_t)(bn + row) * 2048 + k0 + c * 8;
        asm volatile("cp.async.cg.shared.global [%0], [%1], 16;" :: "r"(dB), "l"(pB) : "memory");
    }
}

__global__ __launch_bounds__(256, 2)
void gemm3_bf16(const __nv_bfloat16* __restrict__ Ahi, const __nv_bfloat16* __restrict__ Alo,
                const __nv_bfloat16* __restrict__ Bhi, const __nv_bfloat16* __restrict__ Blo,
                float* __restrict__ C, float alpha)
{
    extern __shared__ __align__(128) char dyn[];
    const int tid  = threadIdx.x;
    const int wid  = tid >> 5;
    const int lane = tid & 31;
    const int bm = blockIdx.y * 128;
    const int bn = blockIdx.x * 128;
    const uint32_t dynb = smem_u32(dyn);

    const int wm0 = (wid >> 1) * 32;        // warp M offset (4 warps in M)
    const int wn0 = (wid & 1) * 64;         // warp N offset (2 warps in N)

    // per-lane ldmatrix offsets (within a 16x16 / 16x(2x8) tile, rows stride ROWB)
    const int q = lane >> 3, l8 = lane & 7;
    const uint32_t aoff = (uint32_t)((l8 + (q & 1) * 8) * ROWB + (q >> 1) * 16);
    const uint32_t boff = (uint32_t)((l8 + (q >> 1) * 8) * ROWB + (q & 1) * 16);

    float acc[2][8][4];
#pragma unroll
    for (int mf = 0; mf < 2; mf++)
#pragma unroll
        for (int nf = 0; nf < 8; nf++)
#pragma unroll
            for (int j = 0; j < 4; j++) acc[mf][nf][j] = 0.f;

    // prologue: stages 0..2
#pragma unroll
    for (int s = 0; s < 3; s++) {
        uint32_t base = dynb + s * STG_BYTES;
        ld_stage(base, base + 128 * ROWB, Ahi, Bhi, bm, bn, s * BKT, tid);
        asm volatile("cp.async.commit_group;" ::: "memory");
    }

    for (int kt = 0; kt < NKT; kt++) {
        asm volatile("cp.async.wait_group 2;" ::: "memory");
        __syncthreads();

        // issue load for kt+3 into buffer (kt+3)%4 (freed by last iter's compute)
        {
            int ktn = kt + 3;
            if (ktn < NKT) {
                int seg = ktn >> 6;
                int k0  = (ktn & 63) * BKT;
                const __nv_bfloat16* As_ = (seg < 2) ? Ahi : Alo;
                const __nv_bfloat16* Bs_ = (seg == 1) ? Blo : Bhi;
                uint32_t base = dynb + (ktn & 3) * STG_BYTES;
                ld_stage(base, base + 128 * ROWB, As_, Bs_, bm, bn, k0, tid);
            }
            asm volatile("cp.async.commit_group;" ::: "memory");
        }

        // compute stage kt%4
        const uint32_t sA = dynb + (kt & 3) * STG_BYTES;
        const uint32_t sB = sA + 128 * ROWB;
#pragma unroll
        for (int ks = 0; ks < 2; ks++) {
            uint32_t a[2][4];
#pragma unroll
            for (int mf = 0; mf < 2; mf++)
                ldm_x4(a[mf], sA + (uint32_t)(wm0 + mf * 16) * ROWB + ks * 32 + aoff);
            uint32_t b[4][4];
#pragma unroll
            for (int p = 0; p < 4; p++)
                ldm_x4(b[p], sB + (uint32_t)(wn0 + p * 16) * ROWB + ks * 32 + boff);
#pragma unroll
            for (int mf = 0; mf < 2; mf++)
#pragma unroll
                for (int p = 0; p < 4; p++) {
                    mma16816(acc[mf][2*p],   a[mf], b[p][0], b[p][1]);
                    mma16816(acc[mf][2*p+1], a[mf], b[p][2], b[p][3]);
                }
        }
        __syncthreads();
    }

    // epilogue: direct fp32 stores
    const int r0 = lane >> 2, c0 = (lane & 3) * 2;
#pragma unroll
    for (int mf = 0; mf < 2; mf++) {
        int rowa = bm + wm0 + mf * 16 + r0;
#pragma unroll
        for (int nf = 0; nf < 8; nf++) {
            int col = bn + wn0 + nf * 8 + c0;
            float2 v0 = {alpha * acc[mf][nf][0], alpha * acc[mf][nf][1]};
            float2 v1 = {alpha * acc[mf][nf][2], alpha * acc[mf][nf][3]};
            *(float2*)(C + (size_t)rowa * 2048 + col)       = v0;
            *(float2*)(C + (size_t)(rowa + 8) * 2048 + col) = v1;
        }
    }
}

// ---------------- eta / theta: sigmoid projections (N=16 each) ----------------
__global__ __launch_bounds__(256)
void eta_theta_kernel(const float* __restrict__ X, const float* __restrict__ Weta,
                      const float* __restrict__ Wth, float* __restrict__ Eta,
                      float* __restrict__ Th)
{
    __shared__ float sx[Dd];
    const int tok = blockIdx.x, tid = threadIdx.x;
    for (int i = tid; i < Dd/4; i += 256)
        *(float4*)&sx[i*4] = *(const float4*)(X + (size_t)tok*Dd + i*4);
    __syncthreads();
    const int p  = tid >> 3;
    const int l8 = tid & 7;
    const int h = p & 15, which = p >> 4;
    const float* w = (which ? Wth : Weta) + (size_t)h * Dd;
    float s = 0.f;
    for (int i = l8*4; i < Dd; i += 32) {
        float4 xv = *(float4*)&sx[i];
        float4 wv = *(const float4*)(w + i);
        s += xv.x*wv.x + xv.y*wv.y + xv.z*wv.z + xv.w*wv.w;
    }
    s += __shfl_xor_sync(0xffffffffu, s, 4);
    s += __shfl_xor_sync(0xffffffffu, s, 2);
    s += __shfl_xor_sync(0xffffffffu, s, 1);
    if (l8 == 0) {
        float sig = 1.f / (1.f + expf(-s));
        if (which) Th[(size_t)tok*Hh + h] = 0.1f * sig;
        else       Eta[(size_t)tok*Hh + h] = sig;
    }
}

// ---------------- chunked fast-weight scan ----------------
__global__ __launch_bounds__(256, 1)
void scan_kernel(const float* __restrict__ Q, const float* __restrict__ Kc,
                 const float* __restrict__ Vc, const float* __restrict__ Eta,
                 const float* __restrict__ Th, float* __restrict__ Z)
{
    extern __shared__ float sm[];
    float* sWt   = sm;
    float* sQ    = sWt  + 128*VS;
    float* sKt   = sQ   + 64*132;
    float* sVE   = sKt  + 128*68;
    float* sM    = sVE  + 64*VS;
    float* sLec  = sM   + 64*65;
    float* sElec = sLec + 64;
    float* sCoef = sElec+ 64;
    float* sTh   = sCoef+ 64;

    const int tid = threadIdx.x;
    const int bh  = blockIdx.x;
    const int b = bh >> 4, h = bh & 15;
    const int vs0 = blockIdx.y * VS;

    const size_t tokbase = (size_t)b * Tt;
    const float* Qp = Q  + tokbase*HD + (size_t)h*Kk;
    const float* Kp = Kc + tokbase*HD + (size_t)h*Kk;
    const float* Vp = Vc + tokbase*HD + (size_t)h*Vv + vs0;
    float*       Zp = Z  + tokbase*HD + (size_t)h*Vv + vs0;

    for (int i = tid; i < 128*VS; i += 256) sWt[i] = 0.f;

    for (int ct = 0; ct < NT; ct++) {
        const int t0 = ct * BT;
        __syncthreads();

#pragma unroll
        for (int i = 0; i < 8; i++) {
            int idx = tid + i*256;
            int r = idx >> 5;
            int c = (idx & 31) << 2;
            float4 qv = *(const float4*)(Qp + (size_t)(t0+r)*HD + c);
            *(float4*)&sQ[r*132 + c] = qv;
            float4 kv = *(const float4*)(Kp + (size_t)(t0+r)*HD + c);
            sKt[(c+0)*68 + r] = kv.x;
            sKt[(c+1)*68 + r] = kv.y;
            sKt[(c+2)*68 + r] = kv.z;
            sKt[(c+3)*68 + r] = kv.w;
        }
#pragma unroll
        for (int i = 0; i < 2; i++) {
            int idx = tid + i*256;
            int r = idx >> 3;
            int c = (idx & 7) << 2;
            *(float4*)&sVE[r*VS + c] = *(const float4*)(Vp + (size_t)(t0+r)*HD + c);
        }
        if (tid < 64) {
            size_t tk = (tokbase + t0 + tid) * Hh + h;
            sLec[tid] = logf(fmaxf(Eta[tk], 1e-8f));
            sTh[tid]  = Th[tk];
        }
        __syncthreads();
        if (tid == 0) {
            float c = 0.f;
            for (int t = 0; t < BT; t++) { c += sLec[t]; sLec[t] = c; }
        }
        __syncthreads();
        if (tid < 64) {
            float l = sLec[tid];
            sElec[tid] = expf(l);
            sCoef[tid] = expf(sLec[63] - l) * sTh[tid];
        }
        __syncthreads();

        {   // e = k @ W^T - v
            const int tx = tid & 7, ty = tid >> 3;
            const int v0 = tx << 2;
            const int ta = ty*2, tb = ta + 1;
            float4 va = *(float4*)&sVE[ta*VS + v0];
            float4 vb = *(float4*)&sVE[tb*VS + v0];
            float a0[4] = {-va.x, -va.y, -va.z, -va.w};
            float a1[4] = {-vb.x, -vb.y, -vb.z, -vb.w};
#pragma unroll 8
            for (int kk = 0; kk < Kk; kk++) {
                float4 w = *(float4*)&sWt[kk*VS + v0];
                float ka = sKt[kk*68 + ta];
                float kb = sKt[kk*68 + tb];
                a0[0] += ka*w.x; a0[1] += ka*w.y; a0[2] += ka*w.z; a0[3] += ka*w.w;
                a1[0] += kb*w.x; a1[1] += kb*w.y; a1[2] += kb*w.z; a1[3] += kb*w.w;
            }
            float4 e0 = {a0[0],a0[1],a0[2],a0[3]};
            float4 e1 = {a1[0],a1[1],a1[2],a1[3]};
            *(float4*)&sVE[ta*VS + v0] = e0;
            *(float4*)&sVE[tb*VS + v0] = e1;
        }
        {   // sM[i][j] = (q_i . k_j) * beta * theta_j
            const int tx = tid & 15, ty = tid >> 4;
            const int j0 = tx*4, i0 = ty*4;
            float acc[4][4];
#pragma unroll
            for (int i = 0; i < 4; i++)
#pragma unroll
                for (int j = 0; j < 4; j++) acc[i][j] = 0.f;
#pragma unroll 8
            for (int kk = 0; kk < Kk; kk++) {
                float4 bj = *(float4*)&sKt[kk*68 + j0];
                float ai0 = sQ[(i0+0)*132 + kk];
                float ai1 = sQ[(i0+1)*132 + kk];
                float ai2 = sQ[(i0+2)*132 + kk];
                float ai3 = sQ[(i0+3)*132 + kk];
                acc[0][0]+=ai0*bj.x; acc[0][1]+=ai0*bj.y; acc[0][2]+=ai0*bj.z; acc[0][3]+=ai0*bj.w;
                acc[1][0]+=ai1*bj.x; acc[1][1]+=ai1*bj.y; acc[1][2]+=ai1*bj.z; acc[1][3]+=ai1*bj.w;
                acc[2][0]+=ai2*bj.x; acc[2][1]+=ai2*bj.y; acc[2][2]+=ai2*bj.z; acc[2][3]+=ai2*bj.w;
                acc[3][0]+=ai3*bj.x; acc[3][1]+=ai3*bj.y; acc[3][2]+=ai3*bj.z; acc[3][3]+=ai3*bj.w;
            }
#pragma unroll
            for (int i = 0; i < 4; i++)
#pragma unroll
                for (int j = 0; j < 4; j++) {
                    int ii = i0 + i, jj = j0 + j;
                    float m = 0.f;
                    if (jj <= ii)
                        m = acc[i][j] * expf(fminf(sLec[ii] - sLec[jj], 0.f)) * sTh[jj];
                    sM[ii*65 + jj] = m;
                }
        }
        __syncthreads();

        {   // z = exp(lec)*(q @ W^T) - sM @ e
            const int tx = tid & 7, ty = tid >> 3;
            const int v0 = tx << 2;
            const int ta = ty*2, tb = ta + 1;
            float z0[4] = {0,0,0,0}, z1[4] = {0,0,0,0};
#pragma unroll 8
            for (int kk = 0; kk < Kk; kk++) {
                float4 w = *(float4*)&sWt[kk*VS + v0];
                float qa = sQ[ta*132 + kk];
                float qb = sQ[tb*132 + kk];
                z0[0]+=qa*w.x; z0[1]+=qa*w.y; z0[2]+=qa*w.z; z0[3]+=qa*w.w;
                z1[0]+=qb*w.x; z1[1]+=qb*w.y; z1[2]+=qb*w.z; z1[3]+=qb*w.w;
            }
            float ea = sElec[ta], eb = sElec[tb];
#pragma unroll
            for (int j = 0; j < 4; j++) { z0[j] *= ea; z1[j] *= eb; }
#pragma unroll 8
            for (int j = 0; j < BT; j++) {
                float4 e4 = *(float4*)&sVE[j*VS + v0];
                float m0 = sM[ta*65 + j];
                float m1 = sM[tb*65 + j];
                z0[0]-=m0*e4.x; z0[1]-=m0*e4.y; z0[2]-=m0*e4.z; z0[3]-=m0*e4.w;
                z1[0]-=m1*e4.x; z1[1]-=m1*e4.y; z1[2]-=m1*e4.z; z1[3]-=m1*e4.w;
            }
            float4 o0 = {z0[0],z0[1],z0[2],z0[3]};
            float4 o1 = {z1[0],z1[1],z1[2],z1[3]};
            *(float4*)(Zp + (size_t)(t0+ta)*HD + v0) = o0;
            *(float4*)(Zp + (size_t)(t0+tb)*HD + v0) = o1;
        }
        __syncthreads();

        {   // W = W*decay - sum_t coef[t]*e^T k
            const int tx = tid & 7, ty = tid >> 3;
            const int v0 = tx << 2, k0 = ty << 2;
            float acc[4][4];
#pragma unroll
            for (int i = 0; i < 4; i++)
#pragma unroll
                for (int j = 0; j < 4; j++) acc[i][j] = 0.f;
            const float decay = sElec[63];
#pragma unroll 4
            for (int t = 0; t < BT; t++) {
                float c = sCoef[t];
                float4 e4 = *(float4*)&sVE[t*VS + v0];
                float ce[4] = {c*e4.x, c*e4.y, c*e4.z, c*e4.w};
                float a0 = sKt[(k0+0)*68 + t];
                float a1 = sKt[(k0+1)*68 + t];
                float a2 = sKt[(k0+2)*68 + t];
                float a3 = sKt[(k0+3)*68 + t];
#pragma unroll
                for (int j = 0; j < 4; j++) {
                    acc[0][j] += a0*ce[j];
                    acc[1][j] += a1*ce[j];
                    acc[2][j] += a2*ce[j];
                    acc[3][j] += a3*ce[j];
                }
            }
#pragma unroll
            for (int i = 0; i < 4; i++) {
                float4 wv = *(float4*)&sWt[(k0+i)*VS + v0];
                wv.x = wv.x*decay - acc[i][0];
                wv.y = wv.y*decay - acc[i][1];
                wv.z = wv.z*decay - acc[i][2];
                wv.w = wv.w*decay - acc[i][3];
                *(float4*)&sWt[(k0+i)*VS + v0] = wv;
            }
        }
    }
}

// ---------------- gated RMS norm -> bf16 hi/lo split ----------------
__global__ __launch_bounds__(256)
void gated_rms_split(const float* __restrict__ Zin, const float* __restrict__ G,
                     const float* __restrict__ nw, __nv_bfloat16* __restrict__ hi,
                     __nv_bfloat16* __restrict__ lo)
{
    const int gw   = blockIdx.x * 8 + (threadIdx.x >> 5);
    const int lane = threadIdx.x & 31;
    const size_t base = (size_t)gw * 128;
    float4 zv = *(const float4*)(Zin + base + lane*4);
    float ss = zv.x*zv.x + zv.y*zv.y + zv.z*zv.z + zv.w*zv.w;
#pragma unroll
    for (int o = 16; o; o >>= 1) ss += __shfl_xor_sync(0xffffffffu, ss, o);
    float r = rsqrtf(ss * (1.f/128.f) + 1e-5f);
    float4 gv = *(const float4*)(G  + base + lane*4);
    float4 wv = *(const float4*)(nw + lane*4);
    float ov[4];
    ov[0] = zv.x*r*wv.x * (gv.x / (1.f + expf(-gv.x)));
    ov[1] = zv.y*r*wv.y * (gv.y / (1.f + expf(-gv.y)));
    ov[2] = zv.z*r*wv.z * (gv.z / (1.f + expf(-gv.z)));
    ov[3] = zv.w*r*wv.w * (gv.w / (1.f + expf(-gv.w)));
    __align__(8) __nv_bfloat16 h[4], l[4];
#pragma unroll
    for (int j = 0; j < 4; j++) {
        h[j] = __float2bfloat16(ov[j]);
        l[j] = __float2bfloat16(ov[j] - __bfloat162float(h[j]));
    }
    *(uint2*)(hi + base + lane*4) = *(uint2*)h;
    *(uint2*)(lo + base + lane*4) = *(uint2*)l;
}

// ---------------- launch ----------------
extern "C" void kernel_launch(void* const* d_in, const int* in_sizes, int n_in,
                              void* d_out, int out_size)
{
    const float* X    = (const float*)d_in[0];
    const float* Wq   = (const float*)d_in[1];
    const float* Wk   = (const float*)d_in[2];
    const float* Wv   = (const float*)d_in[3];
    const float* Weta = (const float*)d_in[4];
    const float* Wth  = (const float*)d_in[5];
    const float* Wg   = (const float*)d_in[6];
    const float* nw   = (const float*)d_in[7];
    const float* Wo   = (const float*)d_in[8];
    float* out = (float*)d_out;

    float *q, *k, *v, *g, *z, *eta, *th;
    __nv_bfloat16 *xhi, *xlo, *whi, *wlo, *oghi, *oglo;
    cudaGetSymbolAddress((void**)&q,   g_q);
    cudaGetSymbolAddress((void**)&k,   g_k);
    cudaGetSymbolAddress((void**)&v,   g_v);
    cudaGetSymbolAddress((void**)&g,   g_g);
    cudaGetSymbolAddress((void**)&z,   g_z);
    cudaGetSymbolAddress((void**)&eta, g_eta);
    cudaGetSymbolAddress((void**)&th,  g_theta);
    cudaGetSymbolAddress((void**)&xhi, g_xhi);
    cudaGetSymbolAddress((void**)&xlo, g_xlo);
    cudaGetSymbolAddress((void**)&whi, g_whi);
    cudaGetSymbolAddress((void**)&wlo, g_wlo);
    cudaGetSymbolAddress((void**)&oghi,g_oghi);
    cudaGetSymbolAddress((void**)&oglo,g_oglo);

    const int scan_smem = (128*VS + 64*132 + 128*68 + 64*VS + 64*65 + 4*64) * 4;
    cudaFuncSetAttribute(scan_kernel, cudaFuncAttributeMaxDynamicSharedMemorySize, scan_smem);
    const int gemm_smem = NSTG * STG_BYTES;   // 81920
    cudaFuncSetAttribute(gemm3_bf16, cudaFuncAttributeMaxDynamicSharedMemorySize, gemm_smem);

    const int WN = Dd * Dd;   // 4,194,304 elems per weight

    split_bf16_kernel<<<TOKS*Dd/4/256, 256>>>(X,  xhi, xlo, TOKS*Dd/4);
    split_bf16_kernel<<<WN/4/256, 256>>>(Wq, whi + 0*(size_t)WN, wlo + 0*(size_t)WN, WN/4);
    split_bf16_kernel<<<WN/4/256, 256>>>(Wk, whi + 1*(size_t)WN, wlo + 1*(size_t)WN, WN/4);
    split_bf16_kernel<<<WN/4/256, 256>>>(Wv, whi + 2*(size_t)WN, wlo + 2*(size_t)WN, WN/4);
    split_bf16_kernel<<<WN/4/256, 256>>>(Wg, whi + 3*(size_t)WN, wlo + 3*(size_t)WN, WN/4);
    split_bf16_kernel<<<WN/4/256, 256>>>(Wo, whi + 4*(size_t)WN, wlo + 4*(size_t)WN, WN/4);

    dim3 gg(HD/128, TOKS/128);   // (16, 64)
    const float qscale = 0.08838834764831845f;  // 128^-0.5

    gemm3_bf16<<<gg, 256, gemm_smem>>>(xhi, xlo, whi + 0*(size_t)WN, wlo + 0*(size_t)WN, q, qscale);
    gemm3_bf16<<<gg, 256, gemm_smem>>>(xhi, xlo, whi + 1*(size_t)WN, wlo + 1*(size_t)WN, k, 1.f);
    gemm3_bf16<<<gg, 256, gemm_smem>>>(xhi, xlo, whi + 2*(size_t)WN, wlo + 2*(size_t)WN, v, 1.f);
    gemm3_bf16<<<gg, 256, gemm_smem>>>(xhi, xlo, whi + 3*(size_t)WN, wlo + 3*(size_t)WN, g, 1.f);
    eta_theta_kernel<<<TOKS, 256>>>(X, Weta, Wth, eta, th);

    scan_kernel<<<dim3(Bb*Hh, NVS), 256, scan_smem>>>(q, k, v, eta, th, z);

    gated_rms_split<<<TOKS*Hh/8, 256>>>(z, g, nw, oghi, oglo);
    gemm3_bf16<<<gg, 256, gemm_smem>>>(oghi, oglo, whi + 4*(size_t)WN, wlo + 4*(size_t)WN, out, 1.f);
}